// round 3
// baseline (speedup 1.0000x reference)
#include <cuda_runtime.h>

// SNN Leaky forward (reset='subtract'):
//   mem = 0.5*mem + x_t - spk;  spk = (mem > 1) ? 1 : 0
// x: [128, 64, 4096] f32 -> spk same shape. Pure HBM streaming.
//
// R3 changes vs R2 (40.4us kernel, DRAM 68%, occ 20%):
//  - float2 per thread instead of float4: 131072 threads (2x warps,
//    27.6 warps/SM, occ ~40%). Latency hiding via warp count, since
//    per-thread MLP was proven non-binding in R2.
//  - keep unroll-8 load front-batching + __ldcs/__stcs streaming hints.

#define T_STEPS 128
#define BN2 131072  // (64*4096)/2 float2 columns

__global__ __launch_bounds__(128) void snn_leaky_kernel(
    const float2* __restrict__ x2, float2* __restrict__ o2)
{
    int idx = blockIdx.x * blockDim.x + threadIdx.x;  // 0..BN2-1

    float2 mem = make_float2(0.f, 0.f);
    float2 spk = make_float2(0.f, 0.f);

    const float2* xp = x2 + idx;
    float2* op = o2 + idx;

    for (int t = 0; t < T_STEPS; t += 8) {
        // front-batch 8 independent loads
        float2 a[8];
#pragma unroll
        for (int u = 0; u < 8; u++)
            a[u] = __ldcs(xp + (t + u) * BN2);

#pragma unroll
        for (int u = 0; u < 8; u++) {
            mem.x = 0.5f * mem.x + a[u].x - spk.x;
            mem.y = 0.5f * mem.y + a[u].y - spk.y;

            spk.x = (mem.x > 1.0f) ? 1.0f : 0.0f;
            spk.y = (mem.y > 1.0f) ? 1.0f : 0.0f;

            __stcs(op + (t + u) * BN2, spk);
        }
    }
}

extern "C" void kernel_launch(void* const* d_in, const int* in_sizes, int n_in,
                              void* d_out, int out_size)
{
    const float2* x2 = (const float2*)d_in[0];
    float2* o2 = (float2*)d_out;
    snn_leaky_kernel<<<BN2 / 128, 128>>>(x2, o2);
}